// round 12
// baseline (speedup 1.0000x reference)
#include <cuda_runtime.h>
#include <cuda_bf16.h>
#include <cstdint>
#include <cstddef>

// Fixed problem shapes: x: [B, 512, 64, 64] f32, mask: [64, 64] bool. d=256, N=4096.
#define BMAX   8
#define DDIM   256
#define NPIX   4096

// ---------------- scratch (device globals) ------------------------------------
__device__ __nv_bfloat16 g_Qh[(size_t)BMAX * NPIX * DDIM];  // normalized latter, hole rows [b][qpos][d]
__device__ __nv_bfloat16 g_Kh[(size_t)BMAX * NPIX * DDIM];  // normalized latter, known rows [b][kpos][d]
__device__ __nv_bfloat16 g_Fh[(size_t)BMAX * NPIX * DDIM];  // former, known rows [b][kpos][d]
__device__ int   g_qidx[NPIX];                              // hole pixel indices by rank
__device__ int   g_cnt [2];                                 // [0]=qcnt, [1]=kcnt

// ---------------- ptx helpers --------------------------------------------------
__device__ __forceinline__ uint32_t smem_u32(const void* p) {
    uint32_t a;
    asm("{ .reg .u64 t; cvta.to.shared.u64 t, %1; cvt.u32.u64 %0, t; }" : "=r"(a) : "l"(p));
    return a;
}
__device__ __forceinline__ void ldsm4(uint32_t& r0, uint32_t& r1, uint32_t& r2, uint32_t& r3, uint32_t a) {
    asm volatile("ldmatrix.sync.aligned.m8n8.x4.shared.b16 {%0,%1,%2,%3}, [%4];"
                 : "=r"(r0), "=r"(r1), "=r"(r2), "=r"(r3) : "r"(a));
}
__device__ __forceinline__ void ldsm4t(uint32_t& r0, uint32_t& r1, uint32_t& r2, uint32_t& r3, uint32_t a) {
    asm volatile("ldmatrix.sync.aligned.m8n8.x4.trans.shared.b16 {%0,%1,%2,%3}, [%4];"
                 : "=r"(r0), "=r"(r1), "=r"(r2), "=r"(r3) : "r"(a));
}
__device__ __forceinline__ void mma16816(float* c, uint32_t a0, uint32_t a1, uint32_t a2, uint32_t a3,
                                         uint32_t b0, uint32_t b1) {
    asm volatile("mma.sync.aligned.m16n8k16.row.col.f32.bf16.bf16.f32 "
                 "{%0,%1,%2,%3}, {%4,%5,%6,%7}, {%8,%9}, {%0,%1,%2,%3};"
                 : "+f"(c[0]), "+f"(c[1]), "+f"(c[2]), "+f"(c[3])
                 : "r"(a0), "r"(a1), "r"(a2), "r"(a3), "r"(b0), "r"(b1));
}
__device__ __forceinline__ uint32_t pack_bf2(float lo, float hi) {
    __nv_bfloat162 h = __floats2bfloat162_rn(lo, hi);
    return *(uint32_t*)&h;
}

// Build thread t's 32-pixel mask word (pixels [32t, 32t+32)).
__device__ __forceinline__ unsigned mask_word(const void* maskp, int t, int isu8)
{
    unsigned bits = 0;
    if (isu8) {
        const unsigned* w = (const unsigned*)maskp;       // 8 words = 32 bytes
        #pragma unroll
        for (int i = 0; i < 8; i++) {
            unsigned v = w[t * 8 + i];
            #pragma unroll
            for (int j = 0; j < 4; j++)
                bits |= (unsigned)(((v >> (8 * j)) & 255u) != 0u) << (i * 4 + j);
        }
    } else {
        const uint4* w4 = (const uint4*)maskp;            // 8 uint4 = 32 ints
        #pragma unroll
        for (int i = 0; i < 8; i++) {
            uint4 v = w4[t * 8 + i];
            bits |= (unsigned)(v.x != 0u) << (i * 4 + 0);
            bits |= (unsigned)(v.y != 0u) << (i * 4 + 1);
            bits |= (unsigned)(v.z != 0u) << (i * 4 + 2);
            bits |= (unsigned)(v.w != 0u) << (i * 4 + 3);
        }
    }
    return bits;
}

// ---------------- kernel 1: fused prep (publishes compaction) ------------------
__global__ void k_prep(const float* __restrict__ x, const void* __restrict__ maskp,
                       float* __restrict__ out)
{
    __shared__ float tile[256][36];
    __shared__ float psum[8][32];
    __shared__ float inv_s[32];
    __shared__ int   pp[32], mq[32];
    __shared__ unsigned s_word;
    __shared__ int      s_pref, s_tot;

    const int b  = blockIdx.y;
    const int bx = blockIdx.x;
    const int n0 = bx * 32;
    const int tx = threadIdx.x & 31;
    const int ty = threadIdx.x >> 5;
    const int r0 = threadIdx.x >> 3;
    const int c4 = (threadIdx.x & 7) << 2;

    // ---- inline mask mini-compaction ----
    unsigned acc = 0;
    {
        const unsigned* w = (const unsigned*)maskp;
        #pragma unroll
        for (int i = 0; i < 4; i++) acc |= w[threadIdx.x + i * 256];
    }
    const int isu8 = __syncthreads_or(acc > 1u);
    if (threadIdx.x == 0) { s_pref = 0; s_tot = 0; }
    unsigned wbits = 0;
    if (threadIdx.x < 128) {
        wbits = mask_word(maskp, threadIdx.x, isu8);
        if ((int)threadIdx.x == bx) s_word = wbits;
    }
    __syncthreads();
    if (threadIdx.x < 128) {
        int c = __popc(wbits);
        if ((int)threadIdx.x < bx) atomicAdd(&s_pref, c);
        if (bx == 0 && b == 0)     atomicAdd(&s_tot, c);
    }

    const float* lat = x + ((size_t)b * 512 + 256) * NPIX;
    float* outb = out + (size_t)b * 768 * NPIX;
    const float4 z4 = make_float4(0.f, 0.f, 0.f, 0.f);

    #pragma unroll
    for (int it = 0; it < 8; it++) {
        int r = it * 32 + r0;
        float4 v = *(const float4*)(lat + (size_t)r * NPIX + n0 + c4);
        *(float4*)(&tile[r][c4]) = v;
        *(float4*)(outb + (size_t)(256 + r) * NPIX + n0 + c4) = v;
        *(float4*)(outb + (size_t)(512 + r) * NPIX + n0 + c4) = z4;
    }
    __syncthreads();

    if (bx == 0 && b == 0 && threadIdx.x == 0) {
        g_cnt[0] = s_tot;
        g_cnt[1] = NPIX - s_tot;
    }

    float ss = 0.f;
    for (int r = ty * 32; r < ty * 32 + 32; r++) { float v = tile[r][tx]; ss += v * v; }
    psum[ty][tx] = ss;
    if (threadIdx.x < 32) {
        unsigned wv  = s_word;
        int isq = (wv >> tx) & 1;
        int pm  = s_pref + __popc(wv & ((1u << tx) - 1u));
        pp[tx] = isq ? pm : (n0 + tx - pm);
        mq[tx] = isq;
        if (b == 0 && isq) g_qidx[pm] = n0 + tx;
    }
    __syncthreads();
    if (threadIdx.x < 32) {
        float s = 0.f;
        #pragma unroll
        for (int i = 0; i < 8; i++) s += psum[i][tx];
        inv_s[tx] = 1.0f / (sqrtf(s) + 1e-8f);
    }
    __syncthreads();

    const float inv = inv_s[tx];
    const int   p   = pp[tx];
    const int   isq = mq[tx];
    {
        __nv_bfloat16* dst = (isq ? g_Qh : g_Kh) + ((size_t)b * NPIX + p) * DDIM;
        #pragma unroll
        for (int i = 0; i < 4; i++) {
            int r8 = ty * 8 + i * 64;
            uint32_t w0 = pack_bf2(tile[r8+0][tx]*inv, tile[r8+1][tx]*inv);
            uint32_t w1 = pack_bf2(tile[r8+2][tx]*inv, tile[r8+3][tx]*inv);
            uint32_t w2 = pack_bf2(tile[r8+4][tx]*inv, tile[r8+5][tx]*inv);
            uint32_t w3 = pack_bf2(tile[r8+6][tx]*inv, tile[r8+7][tx]*inv);
            *(uint4*)(dst + r8) = make_uint4(w0, w1, w2, w3);
        }
    }

    __syncthreads();
    const float* fm = x + (size_t)b * 512 * NPIX;
    #pragma unroll
    for (int it = 0; it < 8; it++) {
        int r = it * 32 + r0;
        float4 v = *(const float4*)(fm + (size_t)r * NPIX + n0 + c4);
        *(float4*)(&tile[r][c4]) = v;
        *(float4*)(outb + (size_t)r * NPIX + n0 + c4) = v;
    }
    __syncthreads();
    if (!isq) {
        __nv_bfloat16* df = g_Fh + ((size_t)b * NPIX + p) * DDIM;
        #pragma unroll
        for (int i = 0; i < 4; i++) {
            int r8 = ty * 8 + i * 64;
            uint32_t w0 = pack_bf2(tile[r8+0][tx], tile[r8+1][tx]);
            uint32_t w1 = pack_bf2(tile[r8+2][tx], tile[r8+3][tx]);
            uint32_t w2 = pack_bf2(tile[r8+4][tx], tile[r8+5][tx]);
            uint32_t w3 = pack_bf2(tile[r8+6][tx], tile[r8+7][tx]);
            *(uint4*)(df + r8) = make_uint4(w0, w1, w2, w3);
        }
    }
}

// ---------------- kernel 2: bf16 tensor-core attention, 512 threads -----------
// 512 threads = 2 groups x 8 warps; group g handles key tiles g, g+2, ...
// GEMM1: 4 q-slabs x 2 k-halves per group (warp tile 16q x 32k).
// GEMM2: d split 8 ways (warp owns 32 d-channels, all 64 q) -> 64 accum regs.
#define QOFF    0                      // bf16 [64][256] swizzled      32768
#define QN_OFF  32768                  // int[64]                        256
#define SL_OFF  33024                  // float[64] l accumulators       256
#define KOFF    33280                  // bf16 K tiles, per group 32768
#define FOFF    98816                  // bf16 F tiles, per group 32768
#define POFF    164352                 // bf16 P [64][64] per group 8192
#define OB_OFF  33280                  // f32 [64][258] (reuses K/F region)
#define OSTRIDE 258
#define SMB     180736

#define STAGE_TILE(SRC, DSTB, K0)                                               \
    do {                                                                        \
        _Pragma("unroll")                                                       \
        for (int _i = 0; _i < 8; _i++) {                                        \
            int _idx = tg + _i * 256;                                           \
            int _row = _idx >> 5, _ch = _idx & 31;                              \
            const __nv_bfloat16* _gp = (SRC) + ((size_t)((K0) + _row) * DDIM + _ch * 8); \
            uint32_t _sa = (DSTB) + _row * 512 + ((_ch ^ (_row & 7)) << 4);     \
            asm volatile("cp.async.cg.shared.global [%0], [%1], 16;"            \
                         :: "r"(_sa), "l"(_gp) : "memory");                     \
        }                                                                       \
        asm volatile("cp.async.commit_group;" ::: "memory");                    \
    } while (0)

__global__ void __launch_bounds__(512, 1)
k_attn(float* __restrict__ out)
{
    extern __shared__ char sm[];
    const uint32_t sb = smem_u32(sm);

    const int b    = blockIdx.y;
    const int qcnt = g_cnt[0];
    const int kcnt = g_cnt[1];
    const int q0   = blockIdx.x * 64;
    if (q0 >= qcnt) return;

    const int tid  = threadIdx.x;
    const int lane = tid & 31;
    const int warp = tid >> 5;      // 0..15
    const int g    = warp >> 3;     // key group 0/1
    const int wg   = warp & 7;      // warp within group 0..7
    const int qh   = wg & 3;        // GEMM1: query slab (16 rows)
    const int kh   = wg >> 2;       // GEMM1: key half (32 cols)
    const int tg   = tid & 255;

    // ---- stage Q tile (swizzled bf16 [64][256]); init qn + l ----
    {
        const __nv_bfloat16* Qg = g_Qh + (size_t)b * NPIX * DDIM;
        #pragma unroll
        for (int i = 0; i < 4; i++) {
            int idx = tid + i * 512;
            int row = idx >> 5, ch = idx & 31;
            uint4 v = make_uint4(0u, 0u, 0u, 0u);
            if (q0 + row < qcnt)
                v = *(const uint4*)(Qg + ((size_t)(q0 + row) * DDIM + ch * 8));
            *(uint4*)(sm + QOFF + row * 512 + ((ch ^ (row & 7)) << 4)) = v;
        }
        if (tid < 64) {
            ((int*)(sm + QN_OFF))[tid] = (q0 + tid < qcnt) ? g_qidx[q0 + tid] : -1;
            ((float*)(sm + SL_OFF))[tid] = 0.f;
        }
    }
    __syncthreads();

    const __nv_bfloat16* Kg = g_Kh + (size_t)b * NPIX * DDIM;
    const __nv_bfloat16* Fg = g_Fh + (size_t)b * NPIX * DDIM;
    const int ntt = (kcnt + 63) >> 6;
    const int ntg = (g == 0) ? ((ntt + 1) >> 1) : (ntt >> 1);

    const uint32_t Kbase = sb + KOFF + g * 32768;
    const uint32_t Fbase = sb + FOFF + g * 32768;
    const uint32_t Pbase = sb + POFF + g * 8192;
    const int barid = 1 + g;

    // GEMM1 fragment constants
    const int aRow0 = qh * 16 + (lane & 15);            // 16q slab
    const int aCb   = lane >> 4;
    const int bRowOff = (lane & 7) + ((lane >> 4) << 3);
    const int bCb   = (lane >> 3) & 1;
    // GEMM2 fragment constants
    const int pRow  = lane & 15;                        // + sl*16
    const int pCb   = lane >> 4;
    const int fRowOff = (lane & 7) + (((lane >> 3) & 1) << 3);
    const int fCb   = (lane >> 4) & 1;

    float o[16][4];                                     // 64 accum regs
    #pragma unroll
    for (int j = 0; j < 16; j++) { o[j][0] = o[j][1] = o[j][2] = o[j][3] = 0.f; }
    float la[2] = {0.f, 0.f};                           // [rowhalf] partial l (16q slab)

    if (ntg > 0) { STAGE_TILE(Kg, Kbase, g * 64); STAGE_TILE(Fg, Fbase, g * 64); }

    for (int t = 0; t < ntg; t++) {
        const int k0 = (g + 2 * t) * 64;

        asm volatile("cp.async.wait_group 1;" ::: "memory");     // K_t ready
        asm volatile("bar.sync %0, 256;" :: "r"(barid) : "memory");

        // ---------- GEMM1: warp computes S[16q x 32k] ----------
        float s[4][4];
        #pragma unroll
        for (int j = 0; j < 4; j++) { s[j][0] = s[j][1] = s[j][2] = s[j][3] = 0.f; }

        #pragma unroll
        for (int ks = 0; ks < 16; ks++) {
            uint32_t a0, a1, a2, a3;
            ldsm4(a0, a1, a2, a3,
                  sb + QOFF + aRow0 * 512 + (((2 * ks + aCb) ^ (aRow0 & 7)) << 4));
            #pragma unroll
            for (int nc = 0; nc < 2; nc++) {
                int row = kh * 32 + nc * 16 + bRowOff;
                uint32_t r0, r1, r2, r3;
                ldsm4(r0, r1, r2, r3, Kbase + row * 512 + (((2 * ks + bCb) ^ (row & 7)) << 4));
                mma16816(s[2 * nc],     a0, a1, a2, a3, r0, r1);
                mma16816(s[2 * nc + 1], a0, a1, a2, a3, r2, r3);
            }
        }

        // ---------- exp (bounded scores -> no max), l accum, P -> smem ----------
        const bool tail = (k0 + 64 > kcnt);
        {
            int qrow = qh * 16 + (lane >> 2);
            #pragma unroll
            for (int j = 0; j < 4; j++) {
                int nc = j >> 1, h = j & 1;
                float e0, e1, e2, e3;
                if (tail) {
                    int kb = k0 + kh * 32 + nc * 16 + h * 8 + 2 * (lane & 3);
                    e0 = (kb     < kcnt) ? __expf(s[j][0]) : 0.f;
                    e1 = (kb + 1 < kcnt) ? __expf(s[j][1]) : 0.f;
                    e2 = (kb     < kcnt) ? __expf(s[j][2]) : 0.f;
                    e3 = (kb + 1 < kcnt) ? __expf(s[j][3]) : 0.f;
                } else {
                    e0 = __expf(s[j][0]);
                    e1 = __expf(s[j][1]);
                    e2 = __expf(s[j][2]);
                    e3 = __expf(s[j][3]);
                }
                la[0] += e0 + e1;
                la[1] += e2 + e3;
                int unit = kh * 4 + nc * 2 + h;
                uint32_t a0 = Pbase + qrow * 128 + ((unit ^ (qrow & 7)) << 4) + ((lane & 3) << 2);
                int qrow1 = qrow + 8;
                uint32_t a1 = Pbase + qrow1 * 128 + ((unit ^ (qrow1 & 7)) << 4) + ((lane & 3) << 2);
                *(uint32_t*)(sm + (a0 - sb)) = pack_bf2(e0, e1);
                *(uint32_t*)(sm + (a1 - sb)) = pack_bf2(e2, e3);
            }
        }

        // F_t ready; combined barrier: K consumed + P visible + F ready
        asm volatile("cp.async.wait_group 0;" ::: "memory");
        asm volatile("bar.sync %0, 256;" :: "r"(barid) : "memory");
        if (t + 1 < ntg) STAGE_TILE(Kg, Kbase, (g + 2 * (t + 1)) * 64);

        // ---------- GEMM2: warp owns d-section [wg*32, wg*32+32), all 64 q ----------
        #pragma unroll
        for (int kk = 0; kk < 4; kk++) {
            uint32_t ap[4][4];
            #pragma unroll
            for (int sl = 0; sl < 4; sl++) {
                int row = sl * 16 + pRow;
                ldsm4(ap[sl][0], ap[sl][1], ap[sl][2], ap[sl][3],
                      Pbase + row * 128 + (((2 * kk + pCb) ^ (row & 7)) << 4));
            }
            #pragma unroll
            for (int nb = 0; nb < 2; nb++) {
                int pg = wg * 2 + nb;                   // d16 block
                int row = kk * 16 + fRowOff;
                uint32_t r0, r1, r2, r3;
                ldsm4t(r0, r1, r2, r3, Fbase + row * 512 + (((2 * pg + fCb) ^ (row & 7)) << 4));
                #pragma unroll
                for (int sl = 0; sl < 4; sl++) {
                    mma16816(o[sl * 4 + nb * 2 + 0], ap[sl][0], ap[sl][1], ap[sl][2], ap[sl][3], r0, r1);
                    mma16816(o[sl * 4 + nb * 2 + 1], ap[sl][0], ap[sl][1], ap[sl][2], ap[sl][3], r2, r3);
                }
            }
        }

        asm volatile("bar.sync %0, 256;" :: "r"(barid) : "memory"); // F + P consumed
        if (t + 1 < ntg) STAGE_TILE(Fg, Fbase, (g + 2 * (t + 1)) * 64);
    }

    // ---------- l: quad-reduce, add into shared ----------
    #pragma unroll
    for (int rh = 0; rh < 2; rh++) {
        float v = la[rh];
        v += __shfl_xor_sync(0xffffffffu, v, 1);
        v += __shfl_xor_sync(0xffffffffu, v, 2);
        la[rh] = v;
    }
    if ((lane & 3) == 0) {
        float* slp = (float*)(sm + SL_OFF);
        #pragma unroll
        for (int rh = 0; rh < 2; rh++)
            atomicAdd(&slp[qh * 16 + rh * 8 + (lane >> 2)], la[rh]);
    }
    __syncthreads();   // l complete; K/F regions retired -> Obuf reuse safe

    // ---------- O merge: group1 writes, group0 adds+scales ----------
    float* Ob = (float*)(sm + OB_OFF);
    if (g == 1) {
        #pragma unroll
        for (int sl = 0; sl < 4; sl++) {
            int q = sl * 16 + (lane >> 2);
            #pragma unroll
            for (int nb = 0; nb < 2; nb++)
                #pragma unroll
                for (int h = 0; h < 2; h++) {
                    int idx = sl * 4 + nb * 2 + h;
                    int d = wg * 32 + nb * 16 + h * 8 + 2 * (lane & 3);
                    *(float2*)(Ob + q * OSTRIDE + d)       = make_float2(o[idx][0], o[idx][1]);
                    *(float2*)(Ob + (q + 8) * OSTRIDE + d) = make_float2(o[idx][2], o[idx][3]);
                }
        }
    }
    __syncthreads();
    if (g == 0) {
        const float* slp = (const float*)(sm + SL_OFF);
        #pragma unroll
        for (int sl = 0; sl < 4; sl++) {
            int q = sl * 16 + (lane >> 2);
            float il0 = 1.0f / slp[q];
            float il1 = 1.0f / slp[q + 8];
            #pragma unroll
            for (int nb = 0; nb < 2; nb++)
                #pragma unroll
                for (int h = 0; h < 2; h++) {
                    int idx = sl * 4 + nb * 2 + h;
                    int d = wg * 32 + nb * 16 + h * 8 + 2 * (lane & 3);
                    float2 x0 = *(float2*)(Ob + q * OSTRIDE + d);
                    float2 x1 = *(float2*)(Ob + (q + 8) * OSTRIDE + d);
                    *(float2*)(Ob + q * OSTRIDE + d) =
                        make_float2((o[idx][0] + x0.x) * il0, (o[idx][1] + x0.y) * il0);
                    *(float2*)(Ob + (q + 8) * OSTRIDE + d) =
                        make_float2((o[idx][2] + x1.x) * il1, (o[idx][3] + x1.y) * il1);
                }
        }
    }
    __syncthreads();

    // ---------- coalesced scatter into hole columns ----------
    {
        const int q = tid & 63;
        const int n = ((const int*)(sm + QN_OFF))[q];
        float* ob = out + ((size_t)b * 768 + 512) * NPIX;
        if (n >= 0) {
            for (int r = tid >> 6; r < 256; r += 8)
                ob[(size_t)r * NPIX + n] = Ob[q * OSTRIDE + r];
        }
    }
}

// ---------------- launch ------------------------------------------------------
extern "C" void kernel_launch(void* const* d_in, const int* in_sizes, int n_in,
                              void* d_out, int out_size)
{
    const float* x    = (const float*)d_in[0];
    const void*  mask = d_in[1];
    float*       out  = (float*)d_out;

    const int N = in_sizes[1];                  // 4096
    const int B = in_sizes[0] / (512 * N);      // 8

    k_prep<<<dim3(N / 32, B), 256>>>(x, mask, out);
    cudaFuncSetAttribute(k_attn, cudaFuncAttributeMaxDynamicSharedMemorySize, SMB);
    k_attn<<<dim3(N / 64, B), 512, SMB>>>(out);
}

// round 14
// speedup vs baseline: 1.0140x; 1.0140x over previous
#include <cuda_runtime.h>
#include <cuda_bf16.h>
#include <cstdint>
#include <cstddef>

// Fixed problem shapes: x: [B, 512, 64, 64] f32, mask: [64, 64] bool. d=256, N=4096.
#define BMAX   8
#define DDIM   256
#define NPIX   4096

// ---------------- scratch (device globals) ------------------------------------
__device__ uint8_t       g_Qf[(size_t)BMAX * NPIX * DDIM];  // e4m3 normalized latter, hole rows [b][qpos][d]
__device__ uint8_t       g_Kf[(size_t)BMAX * NPIX * DDIM];  // e4m3 normalized latter, known rows [b][kpos][d]
__device__ __nv_bfloat16 g_Fh[(size_t)BMAX * NPIX * DDIM];  // bf16 former, known rows [b][kpos][d]
__device__ int   g_qidx[NPIX];                              // hole pixel indices by rank
__device__ int   g_cnt [2];                                 // [0]=qcnt, [1]=kcnt

// ---------------- ptx helpers --------------------------------------------------
__device__ __forceinline__ uint32_t smem_u32(const void* p) {
    uint32_t a;
    asm("{ .reg .u64 t; cvta.to.shared.u64 t, %1; cvt.u32.u64 %0, t; }" : "=r"(a) : "l"(p));
    return a;
}
__device__ __forceinline__ void ldsm4(uint32_t& r0, uint32_t& r1, uint32_t& r2, uint32_t& r3, uint32_t a) {
    asm volatile("ldmatrix.sync.aligned.m8n8.x4.shared.b16 {%0,%1,%2,%3}, [%4];"
                 : "=r"(r0), "=r"(r1), "=r"(r2), "=r"(r3) : "r"(a));
}
__device__ __forceinline__ void ldsm4t(uint32_t& r0, uint32_t& r1, uint32_t& r2, uint32_t& r3, uint32_t a) {
    asm volatile("ldmatrix.sync.aligned.m8n8.x4.trans.shared.b16 {%0,%1,%2,%3}, [%4];"
                 : "=r"(r0), "=r"(r1), "=r"(r2), "=r"(r3) : "r"(a));
}
// bf16 m16n8k16 (GEMM2)
__device__ __forceinline__ void mma16816(float* c, uint32_t a0, uint32_t a1, uint32_t a2, uint32_t a3,
                                         uint32_t b0, uint32_t b1) {
    asm volatile("mma.sync.aligned.m16n8k16.row.col.f32.bf16.bf16.f32 "
                 "{%0,%1,%2,%3}, {%4,%5,%6,%7}, {%8,%9}, {%0,%1,%2,%3};"
                 : "+f"(c[0]), "+f"(c[1]), "+f"(c[2]), "+f"(c[3])
                 : "r"(a0), "r"(a1), "r"(a2), "r"(a3), "r"(b0), "r"(b1));
}
// e4m3 m16n8k32 (GEMM1) — portable PTX since sm_89
__device__ __forceinline__ void mma16832f8(float* c, uint32_t a0, uint32_t a1, uint32_t a2, uint32_t a3,
                                           uint32_t b0, uint32_t b1) {
    asm volatile("mma.sync.aligned.m16n8k32.row.col.f32.e4m3.e4m3.f32 "
                 "{%0,%1,%2,%3}, {%4,%5,%6,%7}, {%8,%9}, {%0,%1,%2,%3};"
                 : "+f"(c[0]), "+f"(c[1]), "+f"(c[2]), "+f"(c[3])
                 : "r"(a0), "r"(a1), "r"(a2), "r"(a3), "r"(b0), "r"(b1));
}
__device__ __forceinline__ uint32_t pack_bf2(float lo, float hi) {
    __nv_bfloat162 h = __floats2bfloat162_rn(lo, hi);
    return *(uint32_t*)&h;
}
// pack two floats to e4m3x2: low byte = lo (first k), high byte = hi
__device__ __forceinline__ uint16_t pack_f8x2(float lo, float hi) {
    uint16_t r;
    asm("cvt.rn.satfinite.e4m3x2.f32 %0, %1, %2;" : "=h"(r) : "f"(hi), "f"(lo));
    return r;
}

// Build thread t's 32-pixel mask word (pixels [32t, 32t+32)).
__device__ __forceinline__ unsigned mask_word(const void* maskp, int t, int isu8)
{
    unsigned bits = 0;
    if (isu8) {
        const unsigned* w = (const unsigned*)maskp;
        #pragma unroll
        for (int i = 0; i < 8; i++) {
            unsigned v = w[t * 8 + i];
            #pragma unroll
            for (int j = 0; j < 4; j++)
                bits |= (unsigned)(((v >> (8 * j)) & 255u) != 0u) << (i * 4 + j);
        }
    } else {
        const uint4* w4 = (const uint4*)maskp;
        #pragma unroll
        for (int i = 0; i < 8; i++) {
            uint4 v = w4[t * 8 + i];
            bits |= (unsigned)(v.x != 0u) << (i * 4 + 0);
            bits |= (unsigned)(v.y != 0u) << (i * 4 + 1);
            bits |= (unsigned)(v.z != 0u) << (i * 4 + 2);
            bits |= (unsigned)(v.w != 0u) << (i * 4 + 3);
        }
    }
    return bits;
}

// ---------------- kernel 1: fused prep (publishes compaction) ------------------
__global__ void k_prep(const float* __restrict__ x, const void* __restrict__ maskp,
                       float* __restrict__ out)
{
    __shared__ float tile[256][36];
    __shared__ float psum[8][32];
    __shared__ float inv_s[32];
    __shared__ int   pp[32], mq[32];
    __shared__ unsigned s_word;
    __shared__ int      s_pref, s_tot;

    const int b  = blockIdx.y;
    const int bx = blockIdx.x;
    const int n0 = bx * 32;
    const int tx = threadIdx.x & 31;
    const int ty = threadIdx.x >> 5;
    const int r0 = threadIdx.x >> 3;
    const int c4 = (threadIdx.x & 7) << 2;

    unsigned acc = 0;
    {
        const unsigned* w = (const unsigned*)maskp;
        #pragma unroll
        for (int i = 0; i < 4; i++) acc |= w[threadIdx.x + i * 256];
    }
    const int isu8 = __syncthreads_or(acc > 1u);
    if (threadIdx.x == 0) { s_pref = 0; s_tot = 0; }
    unsigned wbits = 0;
    if (threadIdx.x < 128) {
        wbits = mask_word(maskp, threadIdx.x, isu8);
        if ((int)threadIdx.x == bx) s_word = wbits;
    }
    __syncthreads();
    if (threadIdx.x < 128) {
        int c = __popc(wbits);
        if ((int)threadIdx.x < bx) atomicAdd(&s_pref, c);
        if (bx == 0 && b == 0)     atomicAdd(&s_tot, c);
    }

    const float* lat = x + ((size_t)b * 512 + 256) * NPIX;
    float* outb = out + (size_t)b * 768 * NPIX;
    const float4 z4 = make_float4(0.f, 0.f, 0.f, 0.f);

    #pragma unroll
    for (int it = 0; it < 8; it++) {
        int r = it * 32 + r0;
        float4 v = *(const float4*)(lat + (size_t)r * NPIX + n0 + c4);
        *(float4*)(&tile[r][c4]) = v;
        *(float4*)(outb + (size_t)(256 + r) * NPIX + n0 + c4) = v;
        *(float4*)(outb + (size_t)(512 + r) * NPIX + n0 + c4) = z4;
    }
    __syncthreads();

    if (bx == 0 && b == 0 && threadIdx.x == 0) {
        g_cnt[0] = s_tot;
        g_cnt[1] = NPIX - s_tot;
    }

    float ss = 0.f;
    for (int r = ty * 32; r < ty * 32 + 32; r++) { float v = tile[r][tx]; ss += v * v; }
    psum[ty][tx] = ss;
    if (threadIdx.x < 32) {
        unsigned wv  = s_word;
        int isq = (wv >> tx) & 1;
        int pm  = s_pref + __popc(wv & ((1u << tx) - 1u));
        pp[tx] = isq ? pm : (n0 + tx - pm);
        mq[tx] = isq;
        if (b == 0 && isq) g_qidx[pm] = n0 + tx;
    }
    __syncthreads();
    if (threadIdx.x < 32) {
        float s = 0.f;
        #pragma unroll
        for (int i = 0; i < 8; i++) s += psum[i][tx];
        inv_s[tx] = 1.0f / (sqrtf(s) + 1e-8f);
    }
    __syncthreads();

    const float inv = inv_s[tx];
    const int   p   = pp[tx];
    const int   isq = mq[tx];
    {
        // Q/K packed as e4m3, row-major [pos][256] (256 B rows)
        uint8_t* dst = (isq ? g_Qf : g_Kf) + ((size_t)b * NPIX + p) * DDIM;
        #pragma unroll
        for (int i = 0; i < 4; i++) {
            int r8 = ty * 8 + i * 64;
            uint16_t h0 = pack_f8x2(tile[r8+0][tx]*inv, tile[r8+1][tx]*inv);
            uint16_t h1 = pack_f8x2(tile[r8+2][tx]*inv, tile[r8+3][tx]*inv);
            uint16_t h2 = pack_f8x2(tile[r8+4][tx]*inv, tile[r8+5][tx]*inv);
            uint16_t h3 = pack_f8x2(tile[r8+6][tx]*inv, tile[r8+7][tx]*inv);
            uint2 w = make_uint2((uint32_t)h0 | ((uint32_t)h1 << 16),
                                 (uint32_t)h2 | ((uint32_t)h3 << 16));
            *(uint2*)(dst + r8) = w;
        }
    }

    __syncthreads();
    const float* fm = x + (size_t)b * 512 * NPIX;
    #pragma unroll
    for (int it = 0; it < 8; it++) {
        int r = it * 32 + r0;
        float4 v = *(const float4*)(fm + (size_t)r * NPIX + n0 + c4);
        *(float4*)(&tile[r][c4]) = v;
        *(float4*)(outb + (size_t)r * NPIX + n0 + c4) = v;
    }
    __syncthreads();
    if (!isq) {
        __nv_bfloat16* df = g_Fh + ((size_t)b * NPIX + p) * DDIM;
        #pragma unroll
        for (int i = 0; i < 4; i++) {
            int r8 = ty * 8 + i * 64;
            uint32_t w0 = pack_bf2(tile[r8+0][tx], tile[r8+1][tx]);
            uint32_t w1 = pack_bf2(tile[r8+2][tx], tile[r8+3][tx]);
            uint32_t w2 = pack_bf2(tile[r8+4][tx], tile[r8+5][tx]);
            uint32_t w3 = pack_bf2(tile[r8+6][tx], tile[r8+7][tx]);
            *(uint4*)(df + r8) = make_uint4(w0, w1, w2, w3);
        }
    }
}

// ---------------- kernel 2: fp8 GEMM1 + bf16 GEMM2 attention ------------------
// 256 threads = 2 groups x 4 warps; group g handles key tiles g, g+2, ...
// GEMM1: e4m3 m16n8k32 (Q,K fp8, 256B rows, 8 k-steps). GEMM2: bf16 (P,F).
#define QOFF    0                      // fp8 Q [64][256B] swizzled    16384
#define QN_OFF  16384                  // int[64]                        256
#define SL_OFF  16640                  // float[64]                      256
#define KOFF    16896                  // fp8 K per group 16384; x2    32768
#define FOFF    49664                  // bf16 F per group 32768; x2   65536
#define POFF    115200                 // bf16 P per group 8192; x2    16384
#define OB_OFF  16896                  // f32 [64][258] reuses K/F     66048
#define OSTRIDE 258
#define SMB     131584

// fp8 swizzled unit index within a 256B row (16 units of 16B)
#define USWZ(u, row) ((((u) & 8) | (((u) ^ (row)) & 7)) << 4)

#define STAGE_K8(SRC, DSTB, K0)                                                 \
    do {                                                                        \
        _Pragma("unroll")                                                       \
        for (int _i = 0; _i < 8; _i++) {                                        \
            int _idx = tg + _i * 128;                                           \
            int _row = _idx >> 4, _u = _idx & 15;                               \
            const uint8_t* _gp = (SRC) + ((size_t)((K0) + _row) * DDIM + _u * 16); \
            uint32_t _sa = (DSTB) + _row * 256 + USWZ(_u, _row);                \
            asm volatile("cp.async.cg.shared.global [%0], [%1], 16;"            \
                         :: "r"(_sa), "l"(_gp) : "memory");                     \
        }                                                                       \
        asm volatile("cp.async.commit_group;" ::: "memory");                    \
    } while (0)

#define STAGE_F16(SRC, DSTB, K0)                                                \
    do {                                                                        \
        _Pragma("unroll")                                                       \
        for (int _i = 0; _i < 16; _i++) {                                       \
            int _idx = tg + _i * 128;                                           \
            int _row = _idx >> 5, _ch = _idx & 31;                              \
            const __nv_bfloat16* _gp = (SRC) + ((size_t)((K0) + _row) * DDIM + _ch * 8); \
            uint32_t _sa = (DSTB) + _row * 512 + ((_ch ^ (_row & 7)) << 4);     \
            asm volatile("cp.async.cg.shared.global [%0], [%1], 16;"            \
                         :: "r"(_sa), "l"(_gp) : "memory");                     \
        }                                                                       \
        asm volatile("cp.async.commit_group;" ::: "memory");                    \
    } while (0)

__global__ void __launch_bounds__(256, 1)
k_attn(float* __restrict__ out)
{
    extern __shared__ char sm[];
    const uint32_t sb = smem_u32(sm);

    const int b    = blockIdx.y;
    const int qcnt = g_cnt[0];
    const int kcnt = g_cnt[1];
    const int q0   = blockIdx.x * 64;
    if (q0 >= qcnt) return;

    const int tid  = threadIdx.x;
    const int lane = tid & 31;
    const int warp = tid >> 5;
    const int g    = warp >> 2;     // key group 0/1
    const int wg   = warp & 3;      // warp within group
    const int qh   = wg & 1;        // GEMM1: query half (32 rows)
    const int kh   = wg >> 1;       // GEMM1: key half (32 cols)
    const int tg   = tid & 127;

    // ---- stage Q tile (fp8, swizzled 256B rows); zero rows past qcnt ----
    {
        const uint8_t* Qg = g_Qf + (size_t)b * NPIX * DDIM;
        #pragma unroll
        for (int i = 0; i < 4; i++) {
            int idx = tid + i * 256;
            int row = idx >> 4, u = idx & 15;
            uint4 v = make_uint4(0u, 0u, 0u, 0u);
            if (q0 + row < qcnt)
                v = *(const uint4*)(Qg + ((size_t)(q0 + row) * DDIM + u * 16));
            *(uint4*)(sm + QOFF + row * 256 + USWZ(u, row)) = v;
        }
        if (tid < 64) {
            ((int*)(sm + QN_OFF))[tid] = (q0 + tid < qcnt) ? g_qidx[q0 + tid] : -1;
            ((float*)(sm + SL_OFF))[tid] = 0.f;
        }
    }
    __syncthreads();

    const uint8_t*       Kg = g_Kf + (size_t)b * NPIX * DDIM;
    const __nv_bfloat16* Fg = g_Fh + (size_t)b * NPIX * DDIM;
    const int ntt = (kcnt + 63) >> 6;
    const int ntg = (g == 0) ? ((ntt + 1) >> 1) : (ntt >> 1);

    const uint32_t Kbase = sb + KOFF + g * 16384;
    const uint32_t Fbase = sb + FOFF + g * 32768;
    const uint32_t Pbase = sb + POFF + g * 8192;
    const int barid = 1 + g;

    // GEMM1 fragment constants (fp8 k32; fragment layout == bf16-k16 via b16 ldsm)
    const int aRow0 = qh * 32 + (lane & 15);
    const int aCb   = lane >> 4;                        // k-half (+16 fp8 = +1 unit)
    const int bRowOff = (lane & 7) + ((lane >> 4) << 3);
    const int bCb   = (lane >> 3) & 1;
    // GEMM2 fragment constants (bf16, unchanged)
    const int pRow  = lane & 15;
    const int pCb   = lane >> 4;
    const int fRowOff = (lane & 7) + (((lane >> 3) & 1) << 3);
    const int fCb   = (lane >> 4) & 1;

    float o[32][4];
    #pragma unroll
    for (int j = 0; j < 32; j++) { o[j][0] = o[j][1] = o[j][2] = o[j][3] = 0.f; }
    float la[2][2] = {{0.f, 0.f}, {0.f, 0.f}};

    if (ntg > 0) { STAGE_K8(Kg, Kbase, g * 64); STAGE_F16(Fg, Fbase, g * 64); }

    for (int t = 0; t < ntg; t++) {
        const int k0 = (g + 2 * t) * 64;

        asm volatile("cp.async.wait_group 1;" ::: "memory");     // K_t ready
        asm volatile("bar.sync %0, 128;" :: "r"(barid) : "memory");

        // ---------- GEMM1 (fp8): warp computes S[32q x 32k], 8 k-steps ----------
        float s[2][4][4];
        #pragma unroll
        for (int i = 0; i < 2; i++)
            #pragma unroll
            for (int j = 0; j < 4; j++)
                s[i][j][0] = s[i][j][1] = s[i][j][2] = s[i][j][3] = 0.f;

        #pragma unroll
        for (int ks = 0; ks < 8; ks++) {
            uint32_t a[2][4];
            #pragma unroll
            for (int sl = 0; sl < 2; sl++) {
                int row = aRow0 + sl * 16;
                ldsm4(a[sl][0], a[sl][1], a[sl][2], a[sl][3],
                      sb + QOFF + row * 256 + USWZ(2 * ks + aCb, row));
            }
            #pragma unroll
            for (int nc = 0; nc < 2; nc++) {
                int row = kh * 32 + nc * 16 + bRowOff;
                uint32_t r0, r1, r2, r3;
                ldsm4(r0, r1, r2, r3, Kbase + row * 256 + USWZ(2 * ks + bCb, row));
                #pragma unroll
                for (int sl = 0; sl < 2; sl++) {
                    mma16832f8(s[sl][2 * nc],     a[sl][0], a[sl][1], a[sl][2], a[sl][3], r0, r1);
                    mma16832f8(s[sl][2 * nc + 1], a[sl][0], a[sl][1], a[sl][2], a[sl][3], r2, r3);
                }
            }
        }

        // ---------- exp (bounded scores -> no max), l accum, P -> smem ----------
        const bool tail = (k0 + 64 > kcnt);
        #pragma unroll
        for (int sl = 0; sl < 2; sl++) {
            int qrow = qh * 32 + sl * 16 + (lane >> 2);
            #pragma unroll
            for (int j = 0; j < 4; j++) {
                int nc = j >> 1, h = j & 1;
                float e0, e1, e2, e3;
                if (tail) {
                    int kb = k0 + kh * 32 + nc * 16 + h * 8 + 2 * (lane & 3);
                    e0 = (kb     < kcnt) ? __expf(s[sl][j][0]) : 0.f;
                    e1 = (kb + 1 < kcnt) ? __expf(s[sl][j][1]) : 0.f;
                    e2 = (kb     < kcnt) ? __expf(s[sl][j][2]) : 0.f;
                    e3 = (kb + 1 < kcnt) ? __expf(s[sl][j][3]) : 0.f;
                } else {
                    e0 = __expf(s[sl][j][0]);
                    e1 = __expf(s[sl][j][1]);
                    e2 = __expf(s[sl][j][2]);
                    e3 = __expf(s[sl][j][3]);
                }
                la[sl][0] += e0 + e1;
                la[sl][1] += e2 + e3;
                int unit = kh * 4 + nc * 2 + h;
                uint32_t a0 = Pbase + qrow * 128 + ((unit ^ (qrow & 7)) << 4) + ((lane & 3) << 2);
                int qrow1 = qrow + 8;
                uint32_t a1 = Pbase + qrow1 * 128 + ((unit ^ (qrow1 & 7)) << 4) + ((lane & 3) << 2);
                *(uint32_t*)(sm + (a0 - sb)) = pack_bf2(e0, e1);
                *(uint32_t*)(sm + (a1 - sb)) = pack_bf2(e2, e3);
            }
        }

        // F_t ready; combined barrier: K consumed + P visible + F ready
        asm volatile("cp.async.wait_group 0;" ::: "memory");
        asm volatile("bar.sync %0, 128;" :: "r"(barid) : "memory");
        if (t + 1 < ntg) STAGE_K8(Kg, Kbase, (g + 2 * (t + 1)) * 64);

        // ---------- GEMM2 (bf16): warp owns d-section [wg*64, +64), all 64 q ----------
        #pragma unroll
        for (int kk = 0; kk < 4; kk++) {
            uint32_t ap[4][4];
            #pragma unroll
            for (int sl = 0; sl < 4; sl++) {
                int row = sl * 16 + pRow;
                ldsm4(ap[sl][0], ap[sl][1], ap[sl][2], ap[sl][3],
                      Pbase + row * 128 + (((2 * kk + pCb) ^ (row & 7)) << 4));
            }
            #pragma unroll
            for (int nb = 0; nb < 4; nb++) {
                int pg = wg * 4 + nb;
                int row = kk * 16 + fRowOff;
                uint32_t r0, r1, r2, r3;
                ldsm4t(r0, r1, r2, r3, Fbase + row * 512 + (((2 * pg + fCb) ^ (row & 7)) << 4));
                #pragma unroll
                for (int sl = 0; sl < 4; sl++) {
                    mma16816(o[sl * 8 + 2 * nb],     ap[sl][0], ap[sl][1], ap[sl][2], ap[sl][3], r0, r1);
                    mma16816(o[sl * 8 + 2 * nb + 1], ap[sl][0], ap[sl][1], ap[sl][2], ap[sl][3], r2, r3);
                }
            }
        }

        asm volatile("bar.sync %0, 128;" :: "r"(barid) : "memory"); // F + P consumed
        if (t + 1 < ntg) STAGE_F16(Fg, Fbase, (g + 2 * (t + 1)) * 64);
    }

    // ---------- l: quad-reduce, add into shared ----------
    #pragma unroll
    for (int sl = 0; sl < 2; sl++)
        #pragma unroll
        for (int rh = 0; rh < 2; rh++) {
            float v = la[sl][rh];
            v += __shfl_xor_sync(0xffffffffu, v, 1);
            v += __shfl_xor_sync(0xffffffffu, v, 2);
            la[sl][rh] = v;
        }
    if ((lane & 3) == 0) {
        float* slp = (float*)(sm + SL_OFF);
        #pragma unroll
        for (int sl = 0; sl < 2; sl++)
            #pragma unroll
            for (int rh = 0; rh < 2; rh++)
                atomicAdd(&slp[qh * 32 + sl * 16 + rh * 8 + (lane >> 2)], la[sl][rh]);
    }
    __syncthreads();   // l complete; K/F regions retired -> Obuf reuse safe

    // ---------- O merge: group1 writes, group0 adds+scales ----------
    float* Ob = (float*)(sm + OB_OFF);
    if (g == 1) {
        #pragma unroll
        for (int sl = 0; sl < 4; sl++) {
            int q = sl * 16 + (lane >> 2);
            #pragma unroll
            for (int nb2 = 0; nb2 < 8; nb2++) {
                int d = wg * 64 + nb2 * 8 + 2 * (lane & 3);
                *(float2*)(Ob + q * OSTRIDE + d)       = make_float2(o[sl*8+nb2][0], o[sl*8+nb2][1]);
                *(float2*)(Ob + (q + 8) * OSTRIDE + d) = make_float2(o[sl*8+nb2][2], o[sl*8+nb2][3]);
            }
        }
    }
    __syncthreads();
    if (g == 0) {
        const float* slp = (const float*)(sm + SL_OFF);
        #pragma unroll
        for (int sl = 0; sl < 4; sl++) {
            int q = sl * 16 + (lane >> 2);
            float il0 = 1.0f / slp[q];
            float il1 = 1.0f / slp[q + 8];
            #pragma unroll
            for (int nb2 = 0; nb2 < 8; nb2++) {
                int d = wg * 64 + nb2 * 8 + 2 * (lane & 3);
                float2 x0 = *(float2*)(Ob + q * OSTRIDE + d);
                float2 x1 = *(float2*)(Ob + (q + 8) * OSTRIDE + d);
                *(float2*)(Ob + q * OSTRIDE + d) =
                    make_float2((o[sl*8+nb2][0] + x0.x) * il0, (o[sl*8+nb2][1] + x0.y) * il0);
                *(float2*)(Ob + (q + 8) * OSTRIDE + d) =
                    make_float2((o[sl*8+nb2][2] + x1.x) * il1, (o[sl*8+nb2][3] + x1.y) * il1);
            }
        }
    }
    __syncthreads();

    // ---------- coalesced scatter into hole columns ----------
    {
        const int q = tid & 63;
        const int n = ((const int*)(sm + QN_OFF))[q];
        float* ob = out + ((size_t)b * 768 + 512) * NPIX;
        if (n >= 0) {
            for (int r = tid >> 6; r < 256; r += 4)
                ob[(size_t)r * NPIX + n] = Ob[q * OSTRIDE + r];
        }
    }
}

// ---------------- launch ------------------------------------------------------
extern "C" void kernel_launch(void* const* d_in, const int* in_sizes, int n_in,
                              void* d_out, int out_size)
{
    const float* x    = (const float*)d_in[0];
    const void*  mask = d_in[1];
    float*       out  = (float*)d_out;

    const int N = in_sizes[1];                  // 4096
    const int B = in_sizes[0] / (512 * N);      // 8

    k_prep<<<dim3(N / 32, B), 256>>>(x, mask, out);
    cudaFuncSetAttribute(k_attn, cudaFuncAttributeMaxDynamicSharedMemorySize, SMB);
    k_attn<<<dim3(N / 64, B), 256, SMB>>>(out);
}

// round 15
// speedup vs baseline: 1.0646x; 1.0500x over previous
#include <cuda_runtime.h>
#include <cuda_bf16.h>
#include <cstdint>
#include <cstddef>

// Fixed problem shapes: x: [B, 512, 64, 64] f32, mask: [64, 64] bool. d=256, N=4096.
#define BMAX   8
#define DDIM   256
#define NPIX   4096

// ---------------- scratch (device globals) ------------------------------------
__device__ __nv_bfloat16 g_Qh[(size_t)BMAX * NPIX * DDIM];  // normalized latter, hole rows [b][qpos][d]
__device__ __nv_bfloat16 g_Kh[(size_t)BMAX * NPIX * DDIM];  // normalized latter, known rows [b][kpos][d]
__device__ __nv_bfloat16 g_Fh[(size_t)BMAX * NPIX * DDIM];  // former, known rows [b][kpos][d]
__device__ int   g_qidx[NPIX];                              // hole pixel indices by rank
__device__ int   g_cnt [2];                                 // [0]=qcnt, [1]=kcnt

// ---------------- ptx helpers --------------------------------------------------
__device__ __forceinline__ uint32_t smem_u32(const void* p) {
    uint32_t a;
    asm("{ .reg .u64 t; cvta.to.shared.u64 t, %1; cvt.u32.u64 %0, t; }" : "=r"(a) : "l"(p));
    return a;
}
__device__ __forceinline__ void ldsm4(uint32_t& r0, uint32_t& r1, uint32_t& r2, uint32_t& r3, uint32_t a) {
    asm volatile("ldmatrix.sync.aligned.m8n8.x4.shared.b16 {%0,%1,%2,%3}, [%4];"
                 : "=r"(r0), "=r"(r1), "=r"(r2), "=r"(r3) : "r"(a));
}
__device__ __forceinline__ void ldsm4t(uint32_t& r0, uint32_t& r1, uint32_t& r2, uint32_t& r3, uint32_t a) {
    asm volatile("ldmatrix.sync.aligned.m8n8.x4.trans.shared.b16 {%0,%1,%2,%3}, [%4];"
                 : "=r"(r0), "=r"(r1), "=r"(r2), "=r"(r3) : "r"(a));
}
__device__ __forceinline__ void mma16816(float* c, uint32_t a0, uint32_t a1, uint32_t a2, uint32_t a3,
                                         uint32_t b0, uint32_t b1) {
    asm volatile("mma.sync.aligned.m16n8k16.row.col.f32.bf16.bf16.f32 "
                 "{%0,%1,%2,%3}, {%4,%5,%6,%7}, {%8,%9}, {%0,%1,%2,%3};"
                 : "+f"(c[0]), "+f"(c[1]), "+f"(c[2]), "+f"(c[3])
                 : "r"(a0), "r"(a1), "r"(a2), "r"(a3), "r"(b0), "r"(b1));
}
__device__ __forceinline__ uint32_t pack_bf2(float lo, float hi) {
    __nv_bfloat162 h = __floats2bfloat162_rn(lo, hi);
    return *(uint32_t*)&h;
}

// Build thread t's 32-pixel mask word (pixels [32t, 32t+32)).
__device__ __forceinline__ unsigned mask_word(const void* maskp, int t, int isu8)
{
    unsigned bits = 0;
    if (isu8) {
        const unsigned* w = (const unsigned*)maskp;       // 8 words = 32 bytes
        #pragma unroll
        for (int i = 0; i < 8; i++) {
            unsigned v = w[t * 8 + i];
            #pragma unroll
            for (int j = 0; j < 4; j++)
                bits |= (unsigned)(((v >> (8 * j)) & 255u) != 0u) << (i * 4 + j);
        }
    } else {
        const uint4* w4 = (const uint4*)maskp;            // 8 uint4 = 32 ints
        #pragma unroll
        for (int i = 0; i < 8; i++) {
            uint4 v = w4[t * 8 + i];
            bits |= (unsigned)(v.x != 0u) << (i * 4 + 0);
            bits |= (unsigned)(v.y != 0u) << (i * 4 + 1);
            bits |= (unsigned)(v.z != 0u) << (i * 4 + 2);
            bits |= (unsigned)(v.w != 0u) << (i * 4 + 3);
        }
    }
    return bits;
}

// ---------------- kernel 1: fused prep (publishes compaction) ------------------
__global__ void k_prep(const float* __restrict__ x, const void* __restrict__ maskp,
                       float* __restrict__ out)
{
    __shared__ float tile[256][36];
    __shared__ float psum[8][32];
    __shared__ float inv_s[32];
    __shared__ int   pp[32], mq[32];
    __shared__ unsigned s_word;
    __shared__ int      s_pref, s_tot;

    const int b  = blockIdx.y;
    const int bx = blockIdx.x;
    const int n0 = bx * 32;
    const int tx = threadIdx.x & 31;
    const int ty = threadIdx.x >> 5;
    const int r0 = threadIdx.x >> 3;
    const int c4 = (threadIdx.x & 7) << 2;

    unsigned acc = 0;
    {
        const unsigned* w = (const unsigned*)maskp;
        #pragma unroll
        for (int i = 0; i < 4; i++) acc |= w[threadIdx.x + i * 256];
    }
    const int isu8 = __syncthreads_or(acc > 1u);
    if (threadIdx.x == 0) { s_pref = 0; s_tot = 0; }
    unsigned wbits = 0;
    if (threadIdx.x < 128) {
        wbits = mask_word(maskp, threadIdx.x, isu8);
        if ((int)threadIdx.x == bx) s_word = wbits;
    }
    __syncthreads();
    if (threadIdx.x < 128) {
        int c = __popc(wbits);
        if ((int)threadIdx.x < bx) atomicAdd(&s_pref, c);
        if (bx == 0 && b == 0)     atomicAdd(&s_tot, c);
    }

    const float* lat = x + ((size_t)b * 512 + 256) * NPIX;
    float* outb = out + (size_t)b * 768 * NPIX;
    const float4 z4 = make_float4(0.f, 0.f, 0.f, 0.f);

    #pragma unroll
    for (int it = 0; it < 8; it++) {
        int r = it * 32 + r0;
        float4 v = *(const float4*)(lat + (size_t)r * NPIX + n0 + c4);
        *(float4*)(&tile[r][c4]) = v;
        *(float4*)(outb + (size_t)(256 + r) * NPIX + n0 + c4) = v;
        *(float4*)(outb + (size_t)(512 + r) * NPIX + n0 + c4) = z4;
    }
    __syncthreads();

    if (bx == 0 && b == 0 && threadIdx.x == 0) {
        g_cnt[0] = s_tot;
        g_cnt[1] = NPIX - s_tot;
    }

    float ss = 0.f;
    for (int r = ty * 32; r < ty * 32 + 32; r++) { float v = tile[r][tx]; ss += v * v; }
    psum[ty][tx] = ss;
    if (threadIdx.x < 32) {
        unsigned wv  = s_word;
        int isq = (wv >> tx) & 1;
        int pm  = s_pref + __popc(wv & ((1u << tx) - 1u));
        pp[tx] = isq ? pm : (n0 + tx - pm);
        mq[tx] = isq;
        if (b == 0 && isq) g_qidx[pm] = n0 + tx;
    }
    __syncthreads();
    if (threadIdx.x < 32) {
        float s = 0.f;
        #pragma unroll
        for (int i = 0; i < 8; i++) s += psum[i][tx];
        inv_s[tx] = 1.0f / (sqrtf(s) + 1e-8f);
    }
    __syncthreads();

    const float inv = inv_s[tx];
    const int   p   = pp[tx];
    const int   isq = mq[tx];
    {
        __nv_bfloat16* dst = (isq ? g_Qh : g_Kh) + ((size_t)b * NPIX + p) * DDIM;
        #pragma unroll
        for (int i = 0; i < 4; i++) {
            int r8 = ty * 8 + i * 64;
            uint32_t w0 = pack_bf2(tile[r8+0][tx]*inv, tile[r8+1][tx]*inv);
            uint32_t w1 = pack_bf2(tile[r8+2][tx]*inv, tile[r8+3][tx]*inv);
            uint32_t w2 = pack_bf2(tile[r8+4][tx]*inv, tile[r8+5][tx]*inv);
            uint32_t w3 = pack_bf2(tile[r8+6][tx]*inv, tile[r8+7][tx]*inv);
            *(uint4*)(dst + r8) = make_uint4(w0, w1, w2, w3);
        }
    }

    __syncthreads();
    const float* fm = x + (size_t)b * 512 * NPIX;
    #pragma unroll
    for (int it = 0; it < 8; it++) {
        int r = it * 32 + r0;
        float4 v = *(const float4*)(fm + (size_t)r * NPIX + n0 + c4);
        *(float4*)(&tile[r][c4]) = v;
        *(float4*)(outb + (size_t)r * NPIX + n0 + c4) = v;
    }
    __syncthreads();
    if (!isq) {
        __nv_bfloat16* df = g_Fh + ((size_t)b * NPIX + p) * DDIM;
        #pragma unroll
        for (int i = 0; i < 4; i++) {
            int r8 = ty * 8 + i * 64;
            uint32_t w0 = pack_bf2(tile[r8+0][tx], tile[r8+1][tx]);
            uint32_t w1 = pack_bf2(tile[r8+2][tx], tile[r8+3][tx]);
            uint32_t w2 = pack_bf2(tile[r8+4][tx], tile[r8+5][tx]);
            uint32_t w3 = pack_bf2(tile[r8+6][tx], tile[r8+7][tx]);
            *(uint4*)(df + r8) = make_uint4(w0, w1, w2, w3);
        }
    }
}

// ---------------- kernel 2: bf16 tensor-core attention (R11 mainloop) ----------
// Grid REORDERED to (B, ntiles): working CTAs (q0 < qcnt) occupy the lowest
// contiguous block IDs, so wave 1 is packed with real work (no empty stagger).
#define QOFF    0                      // bf16 [64][256] swizzled      32768
#define QN_OFF  32768                  // int[64]                        256
#define SL_OFF  33024                  // float[64] l accumulators       256
#define KOFF    33280                  // bf16 K tiles, per group 32768
#define FOFF    98816                  // bf16 F tiles, per group 32768
#define POFF    164352                 // bf16 P [64][64] per group 8192
#define OB_OFF  33280                  // f32 [64][258] (reuses K/F region)
#define OSTRIDE 258
#define SMB     180736

#define STAGE_TILE(SRC, DSTB, K0)                                               \
    do {                                                                        \
        _Pragma("unroll")                                                       \
        for (int _i = 0; _i < 16; _i++) {                                       \
            int _idx = tg + _i * 128;                                           \
            int _row = _idx >> 5, _ch = _idx & 31;                              \
            const __nv_bfloat16* _gp = (SRC) + ((size_t)((K0) + _row) * DDIM + _ch * 8); \
            uint32_t _sa = (DSTB) + _row * 512 + ((_ch ^ (_row & 7)) << 4);     \
            asm volatile("cp.async.cg.shared.global [%0], [%1], 16;"            \
                         :: "r"(_sa), "l"(_gp) : "memory");                     \
        }                                                                       \
        asm volatile("cp.async.commit_group;" ::: "memory");                    \
    } while (0)

__global__ void __launch_bounds__(256, 1)
k_attn(float* __restrict__ out)
{
    extern __shared__ char sm[];
    const uint32_t sb = smem_u32(sm);

    const int b    = blockIdx.x;              // batch on X (fast dim)
    const int qcnt = g_cnt[0];
    const int kcnt = g_cnt[1];
    const int q0   = blockIdx.y * 64;         // q-tile on Y (slow dim)
    if (q0 >= qcnt) return;

    const int tid  = threadIdx.x;
    const int lane = tid & 31;
    const int warp = tid >> 5;
    const int g    = warp >> 2;     // key group 0/1
    const int wg   = warp & 3;      // warp within group
    const int qh   = wg & 1;        // GEMM1: query half (32 rows)
    const int kh   = wg >> 1;       // GEMM1: key half (32 cols)
    const int tg   = tid & 127;

    // ---- stage Q tile (swizzled bf16 [64][256]); zero l accumulators ----
    {
        const __nv_bfloat16* Qg = g_Qh + (size_t)b * NPIX * DDIM;
        #pragma unroll
        for (int i = 0; i < 8; i++) {
            int idx = tid + i * 256;
            int row = idx >> 5, ch = idx & 31;
            uint4 v = make_uint4(0u, 0u, 0u, 0u);
            if (q0 + row < qcnt)
                v = *(const uint4*)(Qg + ((size_t)(q0 + row) * DDIM + ch * 8));
            *(uint4*)(sm + QOFF + row * 512 + ((ch ^ (row & 7)) << 4)) = v;
        }
        if (tid < 64) {
            ((int*)(sm + QN_OFF))[tid] = (q0 + tid < qcnt) ? g_qidx[q0 + tid] : -1;
            ((float*)(sm + SL_OFF))[tid] = 0.f;
        }
    }
    __syncthreads();

    const __nv_bfloat16* Kg = g_Kh + (size_t)b * NPIX * DDIM;
    const __nv_bfloat16* Fg = g_Fh + (size_t)b * NPIX * DDIM;
    const int ntt = (kcnt + 63) >> 6;
    const int ntg = (g == 0) ? ((ntt + 1) >> 1) : (ntt >> 1);

    const uint32_t Kbase = sb + KOFF + g * 32768;
    const uint32_t Fbase = sb + FOFF + g * 32768;
    const uint32_t Pbase = sb + POFF + g * 8192;
    const int barid = 1 + g;

    // GEMM1 fragment constants
    const int aRow0 = qh * 32 + (lane & 15);           // slab 0 row
    const int aCb   = lane >> 4;
    const int bRowOff = (lane & 7) + ((lane >> 4) << 3);
    const int bCb   = (lane >> 3) & 1;
    // GEMM2 fragment constants
    const int pRow  = lane & 15;                        // + s*16
    const int pCb   = lane >> 4;
    const int fRowOff = (lane & 7) + (((lane >> 3) & 1) << 3);
    const int fCb   = (lane >> 4) & 1;

    float o[32][4];
    #pragma unroll
    for (int j = 0; j < 32; j++) { o[j][0] = o[j][1] = o[j][2] = o[j][3] = 0.f; }
    float la[2][2] = {{0.f, 0.f}, {0.f, 0.f}};          // [slab][rowhalf] partial l

    if (ntg > 0) { STAGE_TILE(Kg, Kbase, g * 64); STAGE_TILE(Fg, Fbase, g * 64); }

    for (int t = 0; t < ntg; t++) {
        const int k0 = (g + 2 * t) * 64;

        asm volatile("cp.async.wait_group 1;" ::: "memory");     // K_t ready (F_t may pend)
        asm volatile("bar.sync %0, 128;" :: "r"(barid) : "memory");

        // ---------- GEMM1: warp computes S[32q x 32k] ----------
        float s[2][4][4];
        #pragma unroll
        for (int i = 0; i < 2; i++)
            #pragma unroll
            for (int j = 0; j < 4; j++)
                s[i][j][0] = s[i][j][1] = s[i][j][2] = s[i][j][3] = 0.f;

        #pragma unroll
        for (int ks = 0; ks < 16; ks++) {
            uint32_t a[2][4];
            #pragma unroll
            for (int sl = 0; sl < 2; sl++) {
                int row = aRow0 + sl * 16;
                ldsm4(a[sl][0], a[sl][1], a[sl][2], a[sl][3],
                      sb + QOFF + row * 512 + (((2 * ks + aCb) ^ (row & 7)) << 4));
            }
            #pragma unroll
            for (int nc = 0; nc < 2; nc++) {
                int row = kh * 32 + nc * 16 + bRowOff;
                uint32_t r0, r1, r2, r3;
                ldsm4(r0, r1, r2, r3, Kbase + row * 512 + (((2 * ks + bCb) ^ (row & 7)) << 4));
                #pragma unroll
                for (int sl = 0; sl < 2; sl++) {
                    mma16816(s[sl][2 * nc],     a[sl][0], a[sl][1], a[sl][2], a[sl][3], r0, r1);
                    mma16816(s[sl][2 * nc + 1], a[sl][0], a[sl][1], a[sl][2], a[sl][3], r2, r3);
                }
            }
        }

        // ---------- exp (bounded scores -> no max), l accum, P -> smem ----------
        const bool tail = (k0 + 64 > kcnt);
        #pragma unroll
        for (int sl = 0; sl < 2; sl++) {
            int qrow = qh * 32 + sl * 16 + (lane >> 2);
            #pragma unroll
            for (int j = 0; j < 4; j++) {
                int nc = j >> 1, h = j & 1;
                float e0, e1, e2, e3;
                if (tail) {
                    int kb = k0 + kh * 32 + nc * 16 + h * 8 + 2 * (lane & 3);
                    e0 = (kb     < kcnt) ? __expf(s[sl][j][0]) : 0.f;
                    e1 = (kb + 1 < kcnt) ? __expf(s[sl][j][1]) : 0.f;
                    e2 = (kb     < kcnt) ? __expf(s[sl][j][2]) : 0.f;
                    e3 = (kb + 1 < kcnt) ? __expf(s[sl][j][3]) : 0.f;
                } else {
                    e0 = __expf(s[sl][j][0]);
                    e1 = __expf(s[sl][j][1]);
                    e2 = __expf(s[sl][j][2]);
                    e3 = __expf(s[sl][j][3]);
                }
                la[sl][0] += e0 + e1;
                la[sl][1] += e2 + e3;
                int unit = kh * 4 + nc * 2 + h;
                uint32_t a0 = Pbase + qrow * 128 + ((unit ^ (qrow & 7)) << 4) + ((lane & 3) << 2);
                int qrow1 = qrow + 8;
                uint32_t a1 = Pbase + qrow1 * 128 + ((unit ^ (qrow1 & 7)) << 4) + ((lane & 3) << 2);
                *(uint32_t*)(sm + (a0 - sb)) = pack_bf2(e0, e1);
                *(uint32_t*)(sm + (a1 - sb)) = pack_bf2(e2, e3);
            }
        }

        // F_t ready; combined barrier: K consumed + P visible + F ready
        asm volatile("cp.async.wait_group 0;" ::: "memory");
        asm volatile("bar.sync %0, 128;" :: "r"(barid) : "memory");
        if (t + 1 < ntg) STAGE_TILE(Kg, Kbase, (g + 2 * (t + 1)) * 64);

        // ---------- GEMM2: warp owns d-section [wg*64, wg*64+64), all 64 q ----------
        #pragma unroll
        for (int kk = 0; kk < 4; kk++) {
            uint32_t ap[4][4];
            #pragma unroll
            for (int sl = 0; sl < 4; sl++) {
                int row = sl * 16 + pRow;
                ldsm4(ap[sl][0], ap[sl][1], ap[sl][2], ap[sl][3],
                      Pbase + row * 128 + (((2 * kk + pCb) ^ (row & 7)) << 4));
            }
            #pragma unroll
            for (int nb = 0; nb < 4; nb++) {
                int pg = wg * 4 + nb;                   // d16 block
                int row = kk * 16 + fRowOff;
                uint32_t r0, r1, r2, r3;
                ldsm4t(r0, r1, r2, r3, Fbase + row * 512 + (((2 * pg + fCb) ^ (row & 7)) << 4));
                #pragma unroll
                for (int sl = 0; sl < 4; sl++) {
                    mma16816(o[sl * 8 + 2 * nb],     ap[sl][0], ap[sl][1], ap[sl][2], ap[sl][3], r0, r1);
                    mma16816(o[sl * 8 + 2 * nb + 1], ap[sl][0], ap[sl][1], ap[sl][2], ap[sl][3], r2, r3);
                }
            }
        }

        asm volatile("bar.sync %0, 128;" :: "r"(barid) : "memory"); // F + P consumed
        if (t + 1 < ntg) STAGE_TILE(Fg, Fbase, (g + 2 * (t + 1)) * 64);
    }

    // ---------- l: quad-reduce, add into shared ----------
    #pragma unroll
    for (int sl = 0; sl < 2; sl++)
        #pragma unroll
        for (int rh = 0; rh < 2; rh++) {
            float v = la[sl][rh];
            v += __shfl_xor_sync(0xffffffffu, v, 1);
            v += __shfl_xor_sync(0xffffffffu, v, 2);
            la[sl][rh] = v;
        }
    if ((lane & 3) == 0) {
        float* slp = (float*)(sm + SL_OFF);
        #pragma unroll
        for (int sl = 0; sl < 2; sl++)
            #pragma unroll
            for (int rh = 0; rh < 2; rh++)
                atomicAdd(&slp[qh * 32 + sl * 16 + rh * 8 + (lane >> 2)], la[sl][rh]);
    }
    __syncthreads();   // l complete; K/F regions retired -> Obuf reuse safe

    // ---------- O merge: group1 writes, group0 adds+scales ----------
    float* Ob = (float*)(sm + OB_OFF);
    if (g == 1) {
        #pragma unroll
        for (int sl = 0; sl < 4; sl++) {
            int q = sl * 16 + (lane >> 2);
            #pragma unroll
            for (int nb2 = 0; nb2 < 8; nb2++) {
                int d = wg * 64 + nb2 * 8 + 2 * (lane & 3);
                *(float2*)(Ob + q * OSTRIDE + d)       = make_float2(o[sl*8+nb2][0], o[sl*8+nb2][1]);
                *(float2*)(Ob + (q + 8) * OSTRIDE + d) = make_float2(o[sl*8+nb2][2], o[sl*8+nb2][3]);
            }
        }
    }
    __syncthreads();
    if (g == 0) {
        const float* slp = (const float*)(sm + SL_OFF);
        #pragma unroll
        for (int sl = 0; sl < 4; sl++) {
            int q = sl * 16 + (lane >> 2);
            float il0 = 1.0f / slp[q];
            float il1 = 1.0f / slp[q + 8];
            #pragma unroll
            for (int nb2 = 0; nb2 < 8; nb2++) {
                int d = wg * 64 + nb2 * 8 + 2 * (lane & 3);
                float2 x0 = *(float2*)(Ob + q * OSTRIDE + d);
                float2 x1 = *(float2*)(Ob + (q + 8) * OSTRIDE + d);
                *(float2*)(Ob + q * OSTRIDE + d) =
                    make_float2((o[sl*8+nb2][0] + x0.x) * il0, (o[sl*8+nb2][1] + x0.y) * il0);
                *(float2*)(Ob + (q + 8) * OSTRIDE + d) =
                    make_float2((o[sl*8+nb2][2] + x1.x) * il1, (o[sl*8+nb2][3] + x1.y) * il1);
            }
        }
    }
    __syncthreads();

    // ---------- coalesced scatter into hole columns ----------
    {
        const int q = tid & 63;
        const int n = ((const int*)(sm + QN_OFF))[q];
        float* ob = out + ((size_t)b * 768 + 512) * NPIX;
        if (n >= 0) {
            for (int r = tid >> 6; r < 256; r += 4)
                ob[(size_t)r * NPIX + n] = Ob[q * OSTRIDE + r];
        }
    }
}

// ---------------- launch ------------------------------------------------------
extern "C" void kernel_launch(void* const* d_in, const int* in_sizes, int n_in,
                              void* d_out, int out_size)
{
    const float* x    = (const float*)d_in[0];
    const void*  mask = d_in[1];
    float*       out  = (float*)d_out;

    const int N = in_sizes[1];                  // 4096
    const int B = in_sizes[0] / (512 * N);      // 8

    k_prep<<<dim3(N / 32, B), 256>>>(x, mask, out);
    cudaFuncSetAttribute(k_attn, cudaFuncAttributeMaxDynamicSharedMemorySize, SMB);
    // grid (B, ntiles): batch on fast dim -> working q-tiles get the lowest
    // contiguous block IDs, packing wave 1 with real work.
    k_attn<<<dim3(B, N / 64), 256, SMB>>>(out);
}

// round 16
// speedup vs baseline: 1.1688x; 1.0978x over previous
#include <cuda_runtime.h>
#include <cuda_bf16.h>
#include <cstdint>
#include <cstddef>

#define BMAX   8
#define DDIM   256
#define NPIX   4096

__device__ __nv_bfloat16 g_Qh[(size_t)BMAX * NPIX * DDIM];
__device__ __nv_bfloat16 g_Kh[(size_t)BMAX * NPIX * DDIM];
__device__ __nv_bfloat16 g_Fh[(size_t)BMAX * NPIX * DDIM];
__device__ int   g_qidx[NPIX];
__device__ int   g_cnt [2];

__device__ __forceinline__ uint32_t smem_u32(const void* p) {
    uint32_t a;
    asm("{ .reg .u64 t; cvta.to.shared.u64 t, %1; cvt.u32.u64 %0, t; }" : "=r"(a) : "l"(p));
    return a;
}
__device__ __forceinline__ void ldsm4(uint32_t& r0, uint32_t& r1, uint32_t& r2, uint32_t& r3, uint32_t a) {
    asm volatile("ldmatrix.sync.aligned.m8n8.x4.shared.b16 {%0,%1,%2,%3}, [%4];"
                 : "=r"(r0), "=r"(r1), "=r"(r2), "=r"(r3) : "r"(a));
}
__device__ __forceinline__ void ldsm4t(uint32_t& r0, uint32_t& r1, uint32_t& r2, uint32_t& r3, uint32_t a) {
    asm volatile("ldmatrix.sync.aligned.m8n8.x4.trans.shared.b16 {%0,%1,%2,%3}, [%4];"
                 : "=r"(r0), "=r"(r1), "=r"(r2), "=r"(r3) : "r"(a));
}
__device__ __forceinline__ void mma16816(float* c, uint32_t a0, uint32_t a1, uint32_t a2, uint32_t a3,
                                         uint32_t b0, uint32_t b1) {
    asm volatile("mma.sync.aligned.m16n8k16.row.col.f32.bf16.bf16.f32 "
                 "{%0,%1,%2,%3}, {%4,%5,%6,%7}, {%8,%9}, {%0,%1,%2,%3};"
                 : "+f"(c[0]), "+f"(c[1]), "+f"(c[2]), "+f"(c[3])
                 : "r"(a0), "r"(a1), "r"(a2), "r"(a3), "r"(b0), "r"(b1));
}
__device__ __forceinline__ uint32_t pack_bf2(float lo, float hi) {
    __nv_bfloat162 h = __floats2bfloat162_rn(lo, hi);
    return *(uint32_t*)&h;
}

__device__ __forceinline__ unsigned mask_word(const void* maskp, int t, int isu8)
{
    unsigned bits = 0;
    if (isu8) {
        const unsigned* w = (const unsigned*)maskp;
        #pragma unroll
        for (int i = 0; i < 8; i++) {
            unsigned v = w[t * 8 + i];
            #pragma unroll
            for (int j = 0; j < 4; j++)
                bits |= (unsigned)(((v >> (8 * j)) & 255u) != 0u) << (i * 4 + j);
        }
    } else {
        const uint4* w4 = (const uint4*)maskp;
        #pragma unroll
        for (int i = 0; i < 8; i++) {
            uint4 v = w4[t * 8 + i];
            bits |= (unsigned)(v.x != 0u) << (i * 4 + 0);
            bits |= (unsigned)(v.y != 0u) << (i * 4 + 1);
            bits |= (unsigned)(v.z != 0u) << (i * 4 + 2);
            bits |= (unsigned)(v.w != 0u) << (i * 4 + 3);
        }
    }
    return bits;
}

__global__ void k_prep(const float* __restrict__ x, const void* __restrict__ maskp,
                       float* __restrict__ out)
{
    __shared__ float tile[256][36];
    __shared__ float psum[8][32];
    __shared__ float inv_s[32];
    __shared__ int   pp[32], mq[32];
    __shared__ unsigned s_word;
    __shared__ int      s_pref, s_tot;

    const int b  = blockIdx.y;
    const int bx = blockIdx.x;
    const int n0 = bx * 32;
    const int tx = threadIdx.x & 31;
    const int ty = threadIdx.x >> 5;
    const int r0 = threadIdx.x >> 3;
    const int c4 = (threadIdx.x & 7) << 2;

    unsigned acc = 0;
    {
        const unsigned* w = (const unsigned*)maskp;
        #pragma unroll
        for (int i = 0; i < 4; i++) acc |= w[threadIdx.x + i * 256];
    }
    const int isu8 = __syncthreads_or(acc > 1u);
    if (threadIdx.x == 0) { s_pref = 0; s_tot = 0; }
    unsigned wbits = 0;
    if (threadIdx.x < 128) {
        wbits = mask_word(maskp, threadIdx.x, isu8);
        if ((int)threadIdx.x == bx) s_word = wbits;
    }
    __syncthreads();
    if (threadIdx.x < 128) {
        int c = __popc(wbits);
        if ((int)threadIdx.x < bx) atomicAdd(&s_pref, c);
        if (bx == 0 && b == 0)     atomicAdd(&s_tot, c);
    }

    const float* lat = x + ((size_t)b * 512 + 256) * NPIX;
    float* outb = out + (size_t)b * 768 * NPIX;
    const float4 z4 = make_float4(0.f, 0.f, 0.f, 0.f);

    #pragma unroll
    for (int it = 0; it < 8; it++) {
        int r = it * 32 + r0;
        float4 v = *(const float4*)(lat + (size_t)r * NPIX + n0 + c4);
        *(float4*)(&tile[r][c4]) = v;
        *(float4*)(outb + (size_t)(256 + r) * NPIX + n0 + c4) = v;
        *(float4*)(outb + (size_t)(512 + r) * NPIX + n0 + c4) = z4;
    }
    __syncthreads();

    if (bx == 0 && b == 0 && threadIdx.x == 0) {
        g_cnt[0] = s_tot;
        g_cnt[1] = NPIX - s_tot;
    }

    float ss = 0.f;
    for (int r = ty * 32; r < ty * 32 + 32; r++) { float v = tile[r][tx]; ss += v * v; }
    psum[ty][tx] = ss;
    if (threadIdx.x < 32) {
        unsigned wv  = s_word;
        int isq = (wv >> tx) & 1;
        int pm  = s_pref + __popc(wv & ((1u << tx) - 1u));
        pp[tx] = isq ? pm : (n0 + tx - pm);
        mq[tx] = isq;
        if (b == 0 && isq) g_qidx[pm] = n0 + tx;
    }
    __syncthreads();
    if (threadIdx.x < 32) {
        float s = 0.f;
        #pragma unroll
        for (int i = 0; i < 8; i++) s += psum[i][tx];
        inv_s[tx] = 1.0f / (sqrtf(s) + 1e-8f);
    }
    __syncthreads();

    const float inv = inv_s[tx];
    const int   p   = pp[tx];
    const int   isq = mq[tx];
    {
        __nv_bfloat16* dst = (isq ? g_Qh : g_Kh) + ((size_t)b * NPIX + p) * DDIM;
        #pragma unroll
        for (int i = 0; i < 4; i++) {
            int r8 = ty * 8 + i * 64;
            uint32_t w0 = pack_bf2(tile[r8+0][tx]*inv, tile[r8+1][tx]*inv);
            uint32_t w1 = pack_bf2(tile[r8+2][tx]*inv, tile[r8+3][tx]*inv);
            uint32_t w2 = pack_bf2(tile[r8+4][tx]*inv, tile[r8+5][tx]*inv);
            uint32_t w3 = pack_bf2(tile[r8+6][tx]*inv, tile[r8+7][tx]*inv);
            *(uint4*)(dst + r8) = make_uint4(w0, w1, w2, w3);
        }
    }

    __syncthreads();
    const float* fm = x + (size_t)b * 512 * NPIX;
    #pragma unroll
    for (int it = 0; it < 8; it++) {
        int r = it * 32 + r0;
        float4 v = *(const float4*)(fm + (size_t)r * NPIX + n0 + c4);
        *(float4*)(&tile[r][c4]) = v;
        *(float4*)(outb + (size_t)r * NPIX + n0 + c4) = v;
    }
    __syncthreads();
    if (!isq) {
        __nv_bfloat16* df = g_Fh + ((size_t)b * NPIX + p) * DDIM;
        #pragma unroll
        for (int i = 0; i < 4; i++) {
            int r8 = ty * 8 + i * 64;
            uint32_t w0 = pack_bf2(tile[r8+0][tx], tile[r8+1][tx]);
            uint32_t w1 = pack_bf2(tile[r8+2][tx], tile[r8+3][tx]);
            uint32_t w2 = pack_bf2(tile[r8+4][tx], tile[r8+5][tx]);
            uint32_t w3 = pack_bf2(tile[r8+6][tx], tile[r8+7][tx]);
            *(uint4*)(df + r8) = make_uint4(w0, w1, w2, w3);
        }
    }
}

// ---------------- kernel 2: warp-specialized bf16 attention --------------------
#define QOFF    0
#define QN_OFF  32768
#define SL_OFF  33024
#define KOFF    33280
#define FOFF    98816
#define POFF    164352
#define OB_OFF  33280
#define OSTRIDE 258
#define SMB     180736

#define BARSYNC(ID, CNT)  asm volatile("bar.sync %0, %1;"   :: "r"(ID), "r"(CNT) : "memory")
#define BARARR(ID, CNT)   asm volatile("bar.arrive %0, %1;" :: "r"(ID), "r"(CNT) : "memory")
#define CP_COMMIT() asm volatile("cp.async.commit_group;" ::: "memory")
#define CP_WAIT1()  asm volatile("cp.async.wait_group 1;" ::: "memory")
// barrier ids: 1,2 = P_full[0,1]; 3,4 = P_free[0,1]; 5 = CBAR(256); 6 = PBAR(128)

__global__ void __launch_bounds__(384, 1)
k_attn(float* __restrict__ out)
{
    extern __shared__ char sm[];
    const uint32_t sb = smem_u32(sm);

    const int b    = blockIdx.x;
    const int qcnt = g_cnt[0];
    const int kcnt = g_cnt[1];
    const int q0   = blockIdx.y * 64;
    if (q0 >= qcnt) return;

    const int tid  = threadIdx.x;
    const int lane = tid & 31;
    const int warp = tid >> 5;
    const bool prod = (warp < 4);

    const __nv_bfloat16* Qg = g_Qh + (size_t)b * NPIX * DDIM;
    const __nv_bfloat16* Kg = g_Kh + (size_t)b * NPIX * DDIM;
    const __nv_bfloat16* Fg = g_Fh + (size_t)b * NPIX * DDIM;
    const int ntt = (kcnt + 63) >> 6;

    if (tid < 256) {
        #pragma unroll
        for (int i = 0; i < 8; i++) {
            int idx = tid + i * 256;
            int row = idx >> 5, ch = idx & 31;
            const __nv_bfloat16* gp = Qg + (size_t)(q0 + row) * DDIM + ch * 8;
            uint32_t sa = sb + QOFF + row * 512 + ((ch ^ (row & 7)) << 4);
            uint32_t sz = (q0 + row < qcnt) ? 16u : 0u;
            asm volatile("cp.async.cg.shared.global [%0], [%1], 16, %2;"
                         :: "r"(sa), "l"(gp), "r"(sz) : "memory");
        }
    }
    if (tid < 64) {
        ((int*)(sm + QN_OFF))[tid] = (q0 + tid < qcnt) ? g_qidx[q0 + tid] : -1;
        ((float*)(sm + SL_OFF))[tid] = 0.f;
    }

    if (prod) {
        #pragma unroll
        for (int i = 0; i < 16; i++) {
            int idx = tid + i * 128;
            int row = idx >> 5, ch = idx & 31;
            const __nv_bfloat16* gp = Kg + (size_t)row * DDIM + ch * 8;
            uint32_t sa = sb + KOFF + row * 512 + ((ch ^ (row & 7)) << 4);
            asm volatile("cp.async.cg.shared.global [%0], [%1], 16;" :: "r"(sa), "l"(gp) : "memory");
        }
        CP_COMMIT();
        if (ntt > 1) {
            #pragma unroll
            for (int i = 0; i < 16; i++) {
                int idx = tid + i * 128;
                int row = idx >> 5, ch = idx & 31;
                const __nv_bfloat16* gp = Kg + (size_t)(64 + row) * DDIM + ch * 8;
                uint32_t sa = sb + KOFF + 32768 + row * 512 + ((ch ^ (row & 7)) << 4);
                asm volatile("cp.async.cg.shared.global [%0], [%1], 16;" :: "r"(sa), "l"(gp) : "memory");
            }
        }
        CP_COMMIT();
    } else {
        const int ct = tid - 128;
        #pragma unroll
        for (int i = 0; i < 8; i++) {
            int idx = ct + i * 256;
            int row = idx >> 5, ch = idx & 31;
            const __nv_bfloat16* gp = Fg + (size_t)row * DDIM + ch * 8;
            uint32_t sa = sb + FOFF + row * 512 + ((ch ^ (row & 7)) << 4);
            asm volatile("cp.async.cg.shared.global [%0], [%1], 16;" :: "r"(sa), "l"(gp) : "memory");
        }
        CP_COMMIT();
        if (ntt > 1) {
            #pragma unroll
            for (int i = 0; i < 8; i++) {
                int idx = ct + i * 256;
                int row = idx >> 5, ch = idx & 31;
                const __nv_bfloat16* gp = Fg + (size_t)(64 + row) * DDIM + ch * 8;
                uint32_t sa = sb + FOFF + 32768 + row * 512 + ((ch ^ (row & 7)) << 4);
                asm volatile("cp.async.cg.shared.global [%0], [%1], 16;" :: "r"(sa), "l"(gp) : "memory");
            }
        }
        CP_COMMIT();
    }

    CP_WAIT1();
    __syncthreads();     // publish Q, K0, F0, qn, SL

    float* Ob = (float*)(sm + OB_OFF);

    if (prod) {
        // ================= PRODUCER: GEMM1 + exp + P ring =================
        const int qh = warp & 1;
        const int kh = warp >> 1;
        const int aRow0 = qh * 32 + (lane & 15);
        const int aCb   = lane >> 4;
        const int bRowOff = (lane & 7) + ((lane >> 4) << 3);
        const int bCb   = (lane >> 3) & 1;
        float la[2][2] = {{0.f, 0.f}, {0.f, 0.f}};

        for (int t = 0; t < ntt; t++) {
            const int slot = t & 1;
            const uint32_t Kb = sb + KOFF + slot * 32768;
            const uint32_t Pb = sb + POFF + slot * 8192;

            CP_WAIT1();
            if (t >= 2) BARSYNC(3 + slot, 384);
            BARSYNC(6, 128);

            float s[2][4][4];
            #pragma unroll
            for (int i = 0; i < 2; i++)
                #pragma unroll
                for (int j = 0; j < 4; j++)
                    s[i][j][0] = s[i][j][1] = s[i][j][2] = s[i][j][3] = 0.f;
            #pragma unroll
            for (int ks = 0; ks < 16; ks++) {
                uint32_t a[2][4];
                #pragma unroll
                for (int sl = 0; sl < 2; sl++) {
                    int row = aRow0 + sl * 16;
                    ldsm4(a[sl][0], a[sl][1], a[sl][2], a[sl][3],
                          sb + QOFF + row * 512 + (((2 * ks + aCb) ^ (row & 7)) << 4));
                }
                #pragma unroll
                for (int nc = 0; nc < 2; nc++) {
                    int row = kh * 32 + nc * 16 + bRowOff;
                    uint32_t r0, r1, r2, r3;
                    ldsm4(r0, r1, r2, r3, Kb + row * 512 + (((2 * ks + bCb) ^ (row & 7)) << 4));
                    #pragma unroll
                    for (int sl = 0; sl < 2; sl++) {
                        mma16816(s[sl][2 * nc],     a[sl][0], a[sl][1], a[sl][2], a[sl][3], r0, r1);
                        mma16816(s[sl][2 * nc + 1], a[sl][0], a[sl][1], a[sl][2], a[sl][3], r2, r3);
                    }
                }
            }

            const int k0 = t * 64;
            const bool tail = (k0 + 64 > kcnt);
            #pragma unroll
            for (int sl = 0; sl < 2; sl++) {
                int qrow = qh * 32 + sl * 16 + (lane >> 2);
                #pragma unroll
                for (int j = 0; j < 4; j++) {
                    int nc = j >> 1, h = j & 1;
                    float e0, e1, e2, e3;
                    if (tail) {
                        int kb = k0 + kh * 32 + nc * 16 + h * 8 + 2 * (lane & 3);
                        e0 = (kb     < kcnt) ? __expf(s[sl][j][0]) : 0.f;
                        e1 = (kb + 1 < kcnt) ? __expf(s[sl][j][1]) : 0.f;
                        e2 = (kb     < kcnt) ? __expf(s[sl][j][2]) : 0.f;
                        e3 = (kb + 1 < kcnt) ? __expf(s[sl][j][3]) : 0.f;
                    } else {
                        e0 = __expf(s[sl][j][0]);
                        e1 = __expf(s[sl][j][1]);
                        e2 = __expf(s[sl][j][2]);
                        e3 = __expf(s[sl][j][3]);
                    }
                    la[sl][0] += e0 + e1;
                    la[sl][1] += e2 + e3;
                    int unit = kh * 4 + nc * 2 + h;
                    uint32_t a0 = Pb + qrow * 128 + ((unit ^ (qrow & 7)) << 4) + ((lane & 3) << 2);
                    int qrow1 = qrow + 8;
                    uint32_t a1 = Pb + qrow1 * 128 + ((unit ^ (qrow1 & 7)) << 4) + ((lane & 3) << 2);
                    *(uint32_t*)(sm + (a0 - sb)) = pack_bf2(e0, e1);
                    *(uint32_t*)(sm + (a1 - sb)) = pack_bf2(e2, e3);
                }
            }

            BARARR(1 + slot, 384);
            BARSYNC(6, 128);

            if (t + 2 < ntt) {
                int kk0 = (t + 2) * 64;
                #pragma unroll
                for (int i = 0; i < 16; i++) {
                    int idx = tid + i * 128;
                    int row = idx >> 5, ch = idx & 31;
                    const __nv_bfloat16* gp = Kg + (size_t)(kk0 + row) * DDIM + ch * 8;
                    uint32_t sa = Kb + row * 512 + ((ch ^ (row & 7)) << 4);
                    asm volatile("cp.async.cg.shared.global [%0], [%1], 16;" :: "r"(sa), "l"(gp) : "memory");
                }
            }
            CP_COMMIT();
        }

        for (int e = (ntt < 2 ? 0 : ntt - 2); e < ntt; e++)
            BARSYNC(3 + (e & 1), 384);

        #pragma unroll
        for (int sl = 0; sl < 2; sl++)
            #pragma unroll
            for (int rh = 0; rh < 2; rh++) {
                float v = la[sl][rh];
                v += __shfl_xor_sync(0xffffffffu, v, 1);
                v += __shfl_xor_sync(0xffffffffu, v, 2);
                la[sl][rh] = v;
            }
        if ((lane & 3) == 0) {
            float* slp = (float*)(sm + SL_OFF);
            #pragma unroll
            for (int sl = 0; sl < 2; sl++)
                #pragma unroll
                for (int rh = 0; rh < 2; rh++)
                    atomicAdd(&slp[qh * 32 + sl * 16 + rh * 8 + (lane >> 2)], la[sl][rh]);
        }

        __syncthreads();     // SL complete; Ob region safe
        __syncthreads();     // consumers wrote Ob
    } else {
        // ================= CONSUMERS: GEMM2 (d-split) =================
        const int wc = warp - 4;
        const int ct = tid - 128;
        const int pRow  = lane & 15;
        const int pCb   = lane >> 4;
        const int fRowOff = (lane & 7) + (((lane >> 3) & 1) << 3);
        const int fCb   = (lane >> 4) & 1;

        float o[16][4];
        #pragma unroll
        for (int j = 0; j < 16; j++) { o[j][0] = o[j][1] = o[j][2] = o[j][3] = 0.f; }

        for (int t = 0; t < ntt; t++) {
            const int slot = t & 1;
            const uint32_t Fb = sb + FOFF + slot * 32768;
            const uint32_t Pb = sb + POFF + slot * 8192;

            CP_WAIT1();
            BARSYNC(1 + slot, 384);

            #pragma unroll
            for (int kk = 0; kk < 4; kk++) {
                uint32_t ap[4][4];
                #pragma unroll
                for (int sl = 0; sl < 4; sl++) {
                    int row = sl * 16 + pRow;
                    ldsm4(ap[sl][0], ap[sl][1], ap[sl][2], ap[sl][3],
                          Pb + row * 128 + (((2 * kk + pCb) ^ (row & 7)) << 4));
                }
                #pragma unroll
                for (int nb = 0; nb < 2; nb++) {
                    int pg = wc * 2 + nb;
                    int row = kk * 16 + fRowOff;
                    uint32_t r0, r1, r2, r3;
                    ldsm4t(r0, r1, r2, r3, Fb + row * 512 + (((2 * pg + fCb) ^ (row & 7)) << 4));
                    #pragma unroll
                    for (int sl = 0; sl < 4; sl++) {
                        mma16816(o[sl * 4 + nb * 2 + 0], ap[sl][0], ap[sl][1], ap[sl][2], ap[sl][3], r0, r1);
                        mma16816(o[sl * 4 + nb * 2 + 1], ap[sl][0], ap[sl][1], ap[sl][2], ap[sl][3], r2, r3);
                    }
                }
            }

            BARARR(3 + slot, 384);
            BARSYNC(5, 256);

            if (t + 2 < ntt) {
                int kk0 = (t + 2) * 64;
                #pragma unroll
                for (int i = 0; i < 8; i++) {
                    int idx = ct + i * 256;
                    int row = idx >> 5, ch = idx & 31;
                    const __nv_bfloat16* gp = Fg + (size_t)(kk0 + row) * DDIM + ch * 8;
                    uint32_t sa = Fb + row * 512 + ((ch ^ (row & 7)) << 4);
                    asm volatile("cp.async.cg.shared.global [%0], [%1], 16;" :: "r"(sa), "l"(gp) : "memory");
                }
            }
            CP_COMMIT();
        }

        __syncthreads();     // SL complete; K/F retired -> Ob safe

        const float* slp = (const float*)(sm + SL_OFF);
        #pragma unroll
        for (int sl = 0; sl < 4; sl++) {
            int q = sl * 16 + (lane >> 2);
            float il0 = 1.0f / slp[q];
            float il1 = 1.0f / slp[q + 8];
            #pragma unroll
            for (int nb = 0; nb < 2; nb++)
                #pragma unroll
                for (int h = 0; h < 2; h++) {
                    int idx = sl * 4 + nb * 2 + h;
                    int d = wc * 32 + nb * 16 + h * 8 + 2 * (lane & 3);
                    *(float2*)(Ob + q * OSTRIDE + d) =
                        make_float2(o[idx][0] * il0, o[idx][1] * il0);
                    *(float2*)(Ob + (q + 8) * OSTRIDE + d) =
                        make_float2(o[idx][2] * il1, o[idx][3] * il1);
                }
        }
        __syncthreads();     // Ob complete
    }

    // ---- coalesced scatter into hole columns (all 384 threads) ----
    {
        const int q = tid & 63;
        const int n = ((const int*)(sm + QN_OFF))[q];
        float* ob = out + ((size_t)b * 768 + 512) * NPIX;
        if (n >= 0) {
            for (int r = tid >> 6; r < 256; r += 6)
                ob[(size_t)r * NPIX + n] = Ob[q * OSTRIDE + r];
        }
    }
}

// ---------------- launch ------------------------------------------------------
extern "C" void kernel_launch(void* const* d_in, const int* in_sizes, int n_in,
                              void* d_out, int out_size)
{
    const float* x    = (const float*)d_in[0];
    const void*  mask = d_in[1];
    float*       out  = (float*)d_out;

    const int N = in_sizes[1];                  // 4096
    const int B = in_sizes[0] / (512 * N);      // 8

    k_prep<<<dim3(N / 32, B), 256>>>(x, mask, out);
    cudaFuncSetAttribute(k_attn, cudaFuncAttributeMaxDynamicSharedMemorySize, SMB);
    k_attn<<<dim3(B, N / 64), 384, SMB>>>(out);
}